// round 8
// baseline (speedup 1.0000x reference)
#include <cuda_runtime.h>
#include <cuda_fp16.h>
#include <cstdint>

// ---------------- problem constants ----------------
static constexpr int B = 512, S = 128, D = 512, A = 128;
static constexpr float EPS = 1e-7f;

// ---------------- device scratch (no allocs allowed) ----------------
__device__ __align__(16) __half g_wt[A * D];   // W^T fp16  [a][k]
__device__ float g_kv[B * S];
__device__ float g_mv;

// ---------------- gemm tiling ----------------
static constexpr int KC     = 64;              // k per W chunk
static constexpr int NCHUNK = D / KC;          // 8
static constexpr int STAGES = 3;

// W stage: [128 rows][72 h] (64 data + 8 pad) = 144 B/row -> 18432 B
static constexpr int WROWB  = 72 * 2;          // 144
static constexpr int WBUF_B = 128 * WROWB;     // 18432
static constexpr int OFF_WH   = 0;
static constexpr int OFF_BIAS = STAGES * WBUF_B;            // 55296
static constexpr int OFF_U    = OFF_BIAS + 512;
static constexpr int OFF_PART = OFF_U + 512;                // float[128][2]
static constexpr int SMEM_TOTAL = OFF_PART + 1024;          // 57344

// ---------------- baseline-ISA helpers (sm_100 plain) ----------------
__device__ __forceinline__ uint32_t smem_u32(const void* p) {
    return (uint32_t)__cvta_generic_to_shared(p);
}

#define CP_ASYNC16(dst, src) \
    asm volatile("cp.async.cg.shared.global [%0], [%1], 16;" :: "r"(dst), "l"(src))
#define CP_COMMIT() asm volatile("cp.async.commit_group;")
#define CP_WAIT_1() asm volatile("cp.async.wait_group 1;")

#define LDSM_X4(r, addr) \
    asm volatile("ldmatrix.sync.aligned.m8n8.x4.shared.b16 {%0,%1,%2,%3}, [%4];" \
        : "=r"((r)[0]), "=r"((r)[1]), "=r"((r)[2]), "=r"((r)[3]) : "r"(addr))

#define MMA_F16(d, a, b0, b1) \
    asm volatile("mma.sync.aligned.m16n8k16.row.col.f32.f16.f16.f32 " \
        "{%0,%1,%2,%3}, {%4,%5,%6,%7}, {%8,%9}, {%0,%1,%2,%3};" \
        : "+f"((d)[0]), "+f"((d)[1]), "+f"((d)[2]), "+f"((d)[3]) \
        : "r"((a)[0]), "r"((a)[1]), "r"((a)[2]), "r"((a)[3]), "r"(b0), "r"(b1))

__device__ __forceinline__ uint32_t f2h2(float a, float b) {
    __half2 h = __floats2half2_rn(a, b);
    return *(uint32_t*)&h;
}

__device__ __forceinline__ float fast_tanh(float x) {
    float a = fabsf(x);
    float t = __expf(-2.0f * a);
    float r = (1.0f - t) / (1.0f + t);
    return copysignf(r, x);
}

// ---------------- kernel 0: transpose W to fp16 ----------------
__global__ void prep_w_kernel(const float* __restrict__ W) {
    int idx = blockIdx.x * blockDim.x + threadIdx.x;
    if (idx < D * A) {
        int k = idx / A, a = idx % A;
        g_wt[a * D + k] = __float2half_rn(W[idx]);
    }
}

// ---------------- kernel 1: fused GEMM + tanh + kv ----------------
// CTA = one batch. A-fragments loaded DIRECTLY from global (LDG.64 per lane,
// sector-perfect), converted in registers, prefetched one k-step ahead.
// W staged via 3-stage cp.async ring (L2-resident).
__global__ __launch_bounds__(256, 2)
void gemm_kv_kernel(const float* __restrict__ x,
                    const float* __restrict__ bias,
                    const float* __restrict__ u) {
    extern __shared__ char smem[];
    const uint32_t sb = smem_u32(smem);
    const int tid = threadIdx.x;
    const int wid = tid >> 5;
    const int l   = tid & 31;
    const int b   = blockIdx.x;

    if (tid < A) {
        *(float*)(smem + OFF_BIAS + tid * 4) = bias[tid];
        *(float*)(smem + OFF_U + tid * 4) = u[tid];
    }

    const int wm = wid >> 1, wn = wid & 1;
    const int m0 = wm * 32, n0 = wn * 64;

    const float* xb = x + (size_t)b * S * D;

    // A lane geometry: row = l>>2 (+8 / +16 / +24), cols = (l&3)*2 (+1, +8)
    const int ar  = l >> 2;
    const int ac2 = (l & 3) << 1;
    const float* aP = xb + (size_t)(m0 + ar) * D + ac2;   // + g*16 per k-step

    // B-fragment ldmatrix pointer (within a W stage)
    const uint32_t bOff = (uint32_t)((n0 + ((l >> 4) << 3) + (l & 7)) * WROWB
                                     + (((l >> 3) & 1) << 3) * 2);

    // W cp.async slot geometry: 1024 ops/chunk -> 4/thread
    const int wr0 = tid >> 3, wj = tid & 7;    // + t*32 rows

    float acc[2][8][4];
    #pragma unroll
    for (int mt = 0; mt < 2; mt++)
        #pragma unroll
        for (int nt = 0; nt < 8; nt++)
            #pragma unroll
            for (int q = 0; q < 4; q++) acc[mt][nt][q] = 0.0f;

    float2 pre[8];
    auto loadA = [&](int g) {
        const float* p = aP + g * 16;
        pre[0] = *(const float2*)(p);
        pre[1] = *(const float2*)(p + 8 * D);
        pre[2] = *(const float2*)(p + 8);
        pre[3] = *(const float2*)(p + 8 * D + 8);
        const float* q = p + 16 * D;
        pre[4] = *(const float2*)(q);
        pre[5] = *(const float2*)(q + 8 * D);
        pre[6] = *(const float2*)(q + 8);
        pre[7] = *(const float2*)(q + 8 * D + 8);
    };

    // ---- prologue: A k-step 0 + W chunks 0,1 ----
    loadA(0);
    #pragma unroll
    for (int pc = 0; pc < 2; pc++) {
        const int kk = pc * KC;
        const uint32_t wB = sb + OFF_WH + pc * WBUF_B;
        #pragma unroll
        for (int t = 0; t < 4; t++) {
            int row = wr0 + t * 32;
            CP_ASYNC16(wB + row * WROWB + wj * 16,
                       (const char*)(g_wt + (size_t)row * D + kk) + wj * 16);
        }
        CP_COMMIT();
    }

    #pragma unroll 1
    for (int c = 0; c < NCHUNK; c++) {
        CP_WAIT_1();               // chunk c's W resident
        __syncthreads();

        if (c + 2 < NCHUNK) {
            const int kk = (c + 2) * KC;
            const uint32_t wB = sb + OFF_WH + ((c + 2) % STAGES) * WBUF_B;
            #pragma unroll
            for (int t = 0; t < 4; t++) {
                int row = wr0 + t * 32;
                CP_ASYNC16(wB + row * WROWB + wj * 16,
                           (const char*)(g_wt + (size_t)row * D + kk) + wj * 16);
            }
        }
        CP_COMMIT();               // empty groups keep wait math valid

        const uint32_t wH = sb + OFF_WH + (c % STAGES) * WBUF_B;

        #pragma unroll
        for (int ks = 0; ks < 4; ks++) {
            const int g = c * 4 + ks;
            // convert current prefetch, then launch next k-step's loads
            uint32_t ah[2][4];
            ah[0][0] = f2h2(pre[0].x, pre[0].y);
            ah[0][1] = f2h2(pre[1].x, pre[1].y);
            ah[0][2] = f2h2(pre[2].x, pre[2].y);
            ah[0][3] = f2h2(pre[3].x, pre[3].y);
            ah[1][0] = f2h2(pre[4].x, pre[4].y);
            ah[1][1] = f2h2(pre[5].x, pre[5].y);
            ah[1][2] = f2h2(pre[6].x, pre[6].y);
            ah[1][3] = f2h2(pre[7].x, pre[7].y);
            loadA(g + 1 < 32 ? g + 1 : 31);

            uint32_t bb[4][4];
            #pragma unroll
            for (int nb = 0; nb < 4; nb++)
                LDSM_X4(bb[nb], wH + bOff + nb * (16 * WROWB) + ks * 32);
            #pragma unroll
            for (int mt = 0; mt < 2; mt++)
                #pragma unroll
                for (int nb = 0; nb < 4; nb++) {
                    MMA_F16(acc[mt][2 * nb],     ah[mt], bb[nb][0], bb[nb][1]);
                    MMA_F16(acc[mt][2 * nb + 1], ah[mt], bb[nb][2], bb[nb][3]);
                }
        }
    }
    __syncthreads();

    // ---- epilogue: kv[m] = sum_n tanh(C[m][n] + bias[n]) * u[n] ----
    float rs[2][2] = {{0.0f, 0.0f}, {0.0f, 0.0f}};
    #pragma unroll
    for (int mt = 0; mt < 2; mt++) {
        #pragma unroll
        for (int nt = 0; nt < 8; nt++) {
            int n = n0 + nt * 8 + ((l & 3) << 1);
            float b0v = *(const float*)(smem + OFF_BIAS + n * 4);
            float b1v = *(const float*)(smem + OFF_BIAS + (n + 1) * 4);
            float u0v = *(const float*)(smem + OFF_U + n * 4);
            float u1v = *(const float*)(smem + OFF_U + (n + 1) * 4);
            rs[mt][0] += fast_tanh(acc[mt][nt][0] + b0v) * u0v
                       + fast_tanh(acc[mt][nt][1] + b1v) * u1v;
            rs[mt][1] += fast_tanh(acc[mt][nt][2] + b0v) * u0v
                       + fast_tanh(acc[mt][nt][3] + b1v) * u1v;
        }
    }
    #pragma unroll
    for (int mt = 0; mt < 2; mt++)
        #pragma unroll
        for (int h = 0; h < 2; h++) {
            float v = rs[mt][h];
            v += __shfl_xor_sync(0xFFFFFFFFu, v, 1);
            v += __shfl_xor_sync(0xFFFFFFFFu, v, 2);
            if ((l & 3) == 0) {
                int row = m0 + mt * 16 + h * 8 + (l >> 2);
                *(float*)(smem + OFF_PART + (row * 2 + wn) * 4) = v;
            }
        }
    __syncthreads();
    if (tid < S) {
        float kv = *(const float*)(smem + OFF_PART + (tid * 2) * 4)
                 + *(const float*)(smem + OFF_PART + (tid * 2 + 1) * 4);
        g_kv[b * S + tid] = kv;
    }
}

// ---------------- kernel 2: global sum of kv (double accum) ----------------
__global__ void reduce_kernel() {
    __shared__ double ssum[32];
    double acc = 0.0;
    for (int i = threadIdx.x; i < B * S; i += 1024)
        acc += (double)g_kv[i];
    #pragma unroll
    for (int o = 16; o > 0; o >>= 1)
        acc += __shfl_xor_sync(0xFFFFFFFFu, acc, o);
    if ((threadIdx.x & 31) == 0) ssum[threadIdx.x >> 5] = acc;
    __syncthreads();
    if (threadIdx.x < 32) {
        double v = ssum[threadIdx.x];
        #pragma unroll
        for (int o = 16; o > 0; o >>= 1)
            v += __shfl_xor_sync(0xFFFFFFFFu, v, o);
        if (threadIdx.x == 0) g_mv = (float)v;
    }
}

// ---------------- kernel 3: softmax + weighted pooling (float4) ----------
// Grid {B, 2}; __launch_bounds__(256,7) caps regs at 36 so all 1024 CTAs fit
// in ONE wave (7 * 148 = 1036) -- kills the 1.15-wave tail.
__global__ __launch_bounds__(256, 7)
void softmax_pool_kernel(const float* __restrict__ x,
                         const float* __restrict__ mask,
                         float* __restrict__ out) {
    __shared__ float sprob[S];
    __shared__ float ssum;
    __shared__ float4 spart[4][64];
    const int tid = threadIdx.x;
    const int b = blockIdx.x;
    const int half = blockIdx.y;
    const float mv = g_mv;

    if (tid < S) {
        float e = (expf(g_kv[b * S + tid] - mv) + EPS) * mask[b * S + tid];
        sprob[tid] = e;
    }
    __syncthreads();
    if (tid < 32) {
        float v = sprob[tid] + sprob[tid + 32] + sprob[tid + 64] + sprob[tid + 96];
        #pragma unroll
        for (int o = 16; o > 0; o >>= 1)
            v += __shfl_xor_sync(0xFFFFFFFFu, v, o);
        if (tid == 0) ssum = v;
    }
    __syncthreads();
    const float inv = 1.0f / (ssum + EPS);
    if (tid < S) {
        float p = sprob[tid] * inv;
        sprob[tid] = p;
        if (half == 0) out[B * D + b * S + tid] = p;   // prob output
    }
    __syncthreads();

    // pooling: thread = (sq, dq); dq in [0,64) float4 cols, sq in [0,4)
    const int dq = tid & 63;
    const int sq = tid >> 6;
    const float* xb = x + (size_t)b * S * D + half * 256;
    float4 a0 = make_float4(0.f, 0.f, 0.f, 0.f);
    const int s0 = sq * 32;
    #pragma unroll 4
    for (int s = s0; s < s0 + 32; s++) {
        float4 v = *(const float4*)(xb + (size_t)s * D + dq * 4);
        float p = sprob[s];
        a0.x += v.x * p; a0.y += v.y * p; a0.z += v.z * p; a0.w += v.w * p;
    }
    spart[sq][dq] = a0;
    __syncthreads();
    if (tid < 64) {
        float4 p0 = spart[0][tid], p1 = spart[1][tid];
        float4 p2 = spart[2][tid], p3 = spart[3][tid];
        float4 r = make_float4(p0.x + p1.x + p2.x + p3.x,
                               p0.y + p1.y + p2.y + p3.y,
                               p0.z + p1.z + p2.z + p3.z,
                               p0.w + p1.w + p2.w + p3.w);
        *(float4*)(out + b * D + half * 256 + tid * 4) = r;
    }
}

// ---------------- launcher ----------------
extern "C" void kernel_launch(void* const* d_in, const int* in_sizes, int n_in,
                              void* d_out, int out_size) {
    const float* x    = (const float*)d_in[0];  // inputs  [B,S,D]
    const float* mask = (const float*)d_in[1];  // mask    [B,S,1]
    const float* W    = (const float*)d_in[2];  // kernel  [D,A]
    const float* bias = (const float*)d_in[3];  // bias    [A]
    const float* u    = (const float*)d_in[4];  // u_ctx   [A,1]
    float* out = (float*)d_out;                 // pooled [B,D] ++ prob [B,S]

    cudaFuncSetAttribute(gemm_kv_kernel,
                         cudaFuncAttributeMaxDynamicSharedMemorySize, SMEM_TOTAL);

    prep_w_kernel<<<(D * A + 255) / 256, 256>>>(W);
    gemm_kv_kernel<<<B, 256, SMEM_TOTAL>>>(x, bias, u);
    reduce_kernel<<<1, 1024>>>();
    softmax_pool_kernel<<<dim3(B, 2), 256>>>(x, mask, out);
}

// round 9
// speedup vs baseline: 1.0979x; 1.0979x over previous
#include <cuda_runtime.h>
#include <cuda_fp16.h>
#include <cstdint>

// ---------------- problem constants ----------------
static constexpr int B = 512, S = 128, D = 512, A = 128;
static constexpr float EPS = 1e-7f;

// ---------------- device scratch (no allocs allowed) ----------------
__device__ __align__(16) __half g_wt[A * D];   // W^T fp16  [a][k]
__device__ float g_kv[B * S];
__device__ float g_mv;
__device__ __align__(16) float g_P1[B * D];    // sum_s x*exp(kv)*mask
__device__ __align__(16) float g_P2[B * D];    // sum_s x*mask

// ---------------- gemm tiling ----------------
static constexpr int KC     = 64;              // k per chunk
static constexpr int NCHUNK = D / KC;          // 8
static constexpr int WSTAGES = 3;

// X resident in smem fp16: [128 rows][520 h] (512 data + 8 pad) = 1040 B/row
static constexpr int XROWB  = 520 * 2;         // 1040
static constexpr int XTOT_B = 128 * XROWB;     // 133120
// W stage: [128 rows][72 h] = 144 B/row -> 18432 B
static constexpr int WROWB  = 72 * 2;
static constexpr int WBUF_B = 128 * WROWB;     // 18432
static constexpr int OFF_X    = 0;
static constexpr int OFF_W    = XTOT_B;                     // 133120
static constexpr int OFF_BIAS = OFF_W + WSTAGES * WBUF_B;   // 188416
static constexpr int OFF_U    = OFF_BIAS + 512;
static constexpr int OFF_PART = OFF_U + 512;                // float[128][2]
static constexpr int OFF_W1   = OFF_PART + 1024;            // exp(kv)*mask
static constexpr int OFF_MASK = OFF_W1 + 512;
static constexpr int SMEM_TOTAL = OFF_MASK + 512;           // 191488

// ---------------- baseline-ISA helpers (sm_100 plain) ----------------
__device__ __forceinline__ uint32_t smem_u32(const void* p) {
    return (uint32_t)__cvta_generic_to_shared(p);
}

#define CP_ASYNC16(dst, src) \
    asm volatile("cp.async.cg.shared.global [%0], [%1], 16;" :: "r"(dst), "l"(src))
#define CP_COMMIT() asm volatile("cp.async.commit_group;")
#define CP_WAIT_1() asm volatile("cp.async.wait_group 1;")

#define LDSM_X4(r, addr) \
    asm volatile("ldmatrix.sync.aligned.m8n8.x4.shared.b16 {%0,%1,%2,%3}, [%4];" \
        : "=r"((r)[0]), "=r"((r)[1]), "=r"((r)[2]), "=r"((r)[3]) : "r"(addr))

#define MMA_F16(d, a, b0, b1) \
    asm volatile("mma.sync.aligned.m16n8k16.row.col.f32.f16.f16.f32 " \
        "{%0,%1,%2,%3}, {%4,%5,%6,%7}, {%8,%9}, {%0,%1,%2,%3};" \
        : "+f"((d)[0]), "+f"((d)[1]), "+f"((d)[2]), "+f"((d)[3]) \
        : "r"((a)[0]), "r"((a)[1]), "r"((a)[2]), "r"((a)[3]), "r"(b0), "r"(b1))

__device__ __forceinline__ float fast_tanh(float x) {
    float a = fabsf(x);
    float t = __expf(-2.0f * a);
    float r = (1.0f - t) / (1.0f + t);
    return copysignf(r, x);
}

// ---------------- kernel 0: transpose W to fp16 ----------------
__global__ void prep_w_kernel(const float* __restrict__ W) {
    int idx = blockIdx.x * blockDim.x + threadIdx.x;
    if (idx < D * A) {
        int k = idx / A, a = idx % A;
        g_wt[a * D + k] = __float2half_rn(W[idx]);
    }
}

// ---------------- kernel 1: fused GEMM + tanh + kv + POOLING ----------------
// CTA = one batch. X[b] converted to fp16 and kept resident in smem (read from
// DRAM exactly ONCE). A-frags via ldmatrix on X smem; W via 3-stage cp.async.
// After kv, pooling partials P1/P2 are computed from the resident X tile.
__global__ __launch_bounds__(256, 1)
void gemm_kv_pool_kernel(const float* __restrict__ x,
                         const float* __restrict__ mask,
                         const float* __restrict__ bias,
                         const float* __restrict__ u) {
    extern __shared__ char smem[];
    const uint32_t sb = smem_u32(smem);
    const int tid = threadIdx.x;
    const int wid = tid >> 5;
    const int l   = tid & 31;
    const int b   = blockIdx.x;

    if (tid < A) {
        *(float*)(smem + OFF_BIAS + tid * 4) = bias[tid];
        *(float*)(smem + OFF_U + tid * 4) = u[tid];
        *(float*)(smem + OFF_MASK + tid * 4) = mask[b * S + tid];
    }

    const int wm = wid >> 1, wn = wid & 1;
    const int m0 = wm * 32, n0 = wn * 64;

    const float* xb = x + (size_t)b * S * D;

    // A ldmatrix pointer (hardware-verified scheme from R4): within X smem
    const uint32_t aOff = (uint32_t)((m0 + (l & 15)) * XROWB + ((l >> 4) << 3) * 2);
    // B ldmatrix pointer (within a W stage)
    const uint32_t bOff = (uint32_t)((n0 + ((l >> 4) << 3) + (l & 7)) * WROWB
                                     + (((l >> 3) & 1) << 3) * 2);

    // X LDG geometry: 2048 float4/chunk -> 8/thread
    const int xr0 = tid >> 4, xc4 = tid & 15;     // rows xr0 + t*16
    // W cp.async: 1024 ops/chunk -> 4/thread
    const int wr0 = tid >> 3, wj = tid & 7;       // rows wr0 + t*32

    float acc[2][8][4];
    #pragma unroll
    for (int mt = 0; mt < 2; mt++)
        #pragma unroll
        for (int nt = 0; nt < 8; nt++)
            #pragma unroll
            for (int q = 0; q < 4; q++) acc[mt][nt][q] = 0.0f;

    float4 xreg[8];
    auto loadX = [&](int c) {
        #pragma unroll
        for (int t = 0; t < 8; t++) {
            int row = xr0 + t * 16;
            xreg[t] = *(const float4*)(xb + (size_t)row * D + c * KC + xc4 * 4);
        }
    };
    auto storeX = [&](int c) {
        #pragma unroll
        for (int t = 0; t < 8; t++) {
            int row = xr0 + t * 16;
            __half2 h0 = __floats2half2_rn(xreg[t].x, xreg[t].y);
            __half2 h1 = __floats2half2_rn(xreg[t].z, xreg[t].w);
            *(uint2*)(smem + OFF_X + row * XROWB + (c * KC + xc4 * 4) * 2) =
                make_uint2(*(uint32_t*)&h0, *(uint32_t*)&h1);
        }
    };

    // ---- prologue: X chunk 0 into regs; W chunks 0,1 in flight ----
    loadX(0);
    #pragma unroll
    for (int pc = 0; pc < 2; pc++) {
        const uint32_t wB = sb + OFF_W + pc * WBUF_B;
        #pragma unroll
        for (int t = 0; t < 4; t++) {
            int row = wr0 + t * 32;
            CP_ASYNC16(wB + row * WROWB + wj * 16,
                       (const char*)(g_wt + (size_t)row * D + pc * KC) + wj * 16);
        }
        CP_COMMIT();
    }

    #pragma unroll 1
    for (int c = 0; c < NCHUNK; c++) {
        storeX(c);                      // cvt+STS chunk c from regs
        if (c + 1 < NCHUNK) loadX(c + 1);   // LDGs fill during MMA below
        CP_WAIT_1();                    // W chunk c resident
        __syncthreads();                // X_c + W_c visible

        if (c + 2 < NCHUNK) {
            const uint32_t wB = sb + OFF_W + ((c + 2) % WSTAGES) * WBUF_B;
            #pragma unroll
            for (int t = 0; t < 4; t++) {
                int row = wr0 + t * 32;
                CP_ASYNC16(wB + row * WROWB + wj * 16,
                           (const char*)(g_wt + (size_t)row * D + (c + 2) * KC) + wj * 16);
            }
        }
        CP_COMMIT();                    // empty groups keep wait math valid

        const uint32_t wH = sb + OFF_W + (c % WSTAGES) * WBUF_B;
        #pragma unroll
        for (int ks = 0; ks < 4; ks++) {
            const int g = c * 4 + ks;
            uint32_t ah[2][4], bb[4][4];
            LDSM_X4(ah[0], sb + OFF_X + aOff + g * 32);
            LDSM_X4(ah[1], sb + OFF_X + aOff + 16 * XROWB + g * 32);
            #pragma unroll
            for (int nb = 0; nb < 4; nb++)
                LDSM_X4(bb[nb], wH + bOff + nb * (16 * WROWB) + ks * 32);
            #pragma unroll
            for (int mt = 0; mt < 2; mt++)
                #pragma unroll
                for (int nb = 0; nb < 4; nb++) {
                    MMA_F16(acc[mt][2 * nb],     ah[mt], bb[nb][0], bb[nb][1]);
                    MMA_F16(acc[mt][2 * nb + 1], ah[mt], bb[nb][2], bb[nb][3]);
                }
        }
        __syncthreads();                // MMA done before next chunk's STS
    }

    // ---- kv epilogue: kv[m] = sum_n tanh(C[m][n] + bias[n]) * u[n] ----
    float rs[2][2] = {{0.0f, 0.0f}, {0.0f, 0.0f}};
    #pragma unroll
    for (int mt = 0; mt < 2; mt++) {
        #pragma unroll
        for (int nt = 0; nt < 8; nt++) {
            int n = n0 + nt * 8 + ((l & 3) << 1);
            float b0v = *(const float*)(smem + OFF_BIAS + n * 4);
            float b1v = *(const float*)(smem + OFF_BIAS + (n + 1) * 4);
            float u0v = *(const float*)(smem + OFF_U + n * 4);
            float u1v = *(const float*)(smem + OFF_U + (n + 1) * 4);
            rs[mt][0] += fast_tanh(acc[mt][nt][0] + b0v) * u0v
                       + fast_tanh(acc[mt][nt][1] + b1v) * u1v;
            rs[mt][1] += fast_tanh(acc[mt][nt][2] + b0v) * u0v
                       + fast_tanh(acc[mt][nt][3] + b1v) * u1v;
        }
    }
    #pragma unroll
    for (int mt = 0; mt < 2; mt++)
        #pragma unroll
        for (int h = 0; h < 2; h++) {
            float v = rs[mt][h];
            v += __shfl_xor_sync(0xFFFFFFFFu, v, 1);
            v += __shfl_xor_sync(0xFFFFFFFFu, v, 2);
            if ((l & 3) == 0) {
                int row = m0 + mt * 16 + h * 8 + (l >> 2);
                *(float*)(smem + OFF_PART + (row * 2 + wn) * 4) = v;
            }
        }
    __syncthreads();
    if (tid < S) {
        float kv = *(const float*)(smem + OFF_PART + (tid * 2) * 4)
                 + *(const float*)(smem + OFF_PART + (tid * 2 + 1) * 4);
        g_kv[b * S + tid] = kv;
        float mk = *(const float*)(smem + OFF_MASK + tid * 4);
        *(float*)(smem + OFF_W1 + tid * 4) = __expf(kv) * mk;  // |kv|<=~10, safe
    }
    __syncthreads();

    // ---- pooling partials from resident fp16 X tile ----
    // thread tid owns d-pair {2*tid, 2*tid+1}
    float2 p1 = make_float2(0.f, 0.f), p2 = make_float2(0.f, 0.f);
    #pragma unroll 8
    for (int s = 0; s < S; s++) {
        uint32_t packed = *(const uint32_t*)(smem + OFF_X + s * XROWB + tid * 4);
        float2 f = __half22float2(*(const __half2*)&packed);
        float w1 = *(const float*)(smem + OFF_W1 + s * 4);
        float w2 = *(const float*)(smem + OFF_MASK + s * 4);
        p1.x += f.x * w1; p1.y += f.y * w1;
        p2.x += f.x * w2; p2.y += f.y * w2;
    }
    *(float2*)(g_P1 + (size_t)b * D + tid * 2) = p1;
    *(float2*)(g_P2 + (size_t)b * D + tid * 2) = p2;
}

// ---------------- kernel 2: global sum of kv (double accum) ----------------
__global__ void reduce_kernel() {
    __shared__ double ssum[32];
    double acc = 0.0;
    for (int i = threadIdx.x; i < B * S; i += 1024)
        acc += (double)g_kv[i];
    #pragma unroll
    for (int o = 16; o > 0; o >>= 1)
        acc += __shfl_xor_sync(0xFFFFFFFFu, acc, o);
    if ((threadIdx.x & 31) == 0) ssum[threadIdx.x >> 5] = acc;
    __syncthreads();
    if (threadIdx.x < 32) {
        double v = ssum[threadIdx.x];
        #pragma unroll
        for (int o = 16; o > 0; o >>= 1)
            v += __shfl_xor_sync(0xFFFFFFFFu, v, o);
        if (threadIdx.x == 0) g_mv = (float)v;
    }
}

// ---------------- kernel 3: combine -> prob + pooled (tiny) ----------------
__global__ __launch_bounds__(128)
void combine_kernel(const float* __restrict__ mask, float* __restrict__ out) {
    __shared__ float se[S];
    __shared__ float ssum;
    const int tid = threadIdx.x;
    const int b = blockIdx.x;
    const double mv = (double)g_mv;

    float kv = g_kv[b * S + tid];
    float mk = mask[b * S + tid];
    float e = (float)exp((double)kv - mv);        // matches reference regime-wise
    float kve = (e + EPS) * mk;
    se[tid] = kve;
    __syncthreads();
    if (tid < 32) {
        float v = se[tid] + se[tid + 32] + se[tid + 64] + se[tid + 96];
        #pragma unroll
        for (int o = 16; o > 0; o >>= 1)
            v += __shfl_xor_sync(0xFFFFFFFFu, v, o);
        if (tid == 0) ssum = v;
    }
    __syncthreads();
    const double den = (double)ssum + (double)EPS;
    out[B * D + b * S + tid] = (float)((double)kve / den);   // prob

    const double c = exp(-mv);
    #pragma unroll
    for (int i = tid; i < D; i += 128) {
        double num = c * (double)g_P1[(size_t)b * D + i]
                   + (double)EPS * (double)g_P2[(size_t)b * D + i];
        out[b * D + i] = (float)(num / den);                  // pooled
    }
}

// ---------------- launcher ----------------
extern "C" void kernel_launch(void* const* d_in, const int* in_sizes, int n_in,
                              void* d_out, int out_size) {
    const float* x    = (const float*)d_in[0];  // inputs  [B,S,D]
    const float* mask = (const float*)d_in[1];  // mask    [B,S,1]
    const float* W    = (const float*)d_in[2];  // kernel  [D,A]
    const float* bias = (const float*)d_in[3];  // bias    [A]
    const float* u    = (const float*)d_in[4];  // u_ctx   [A,1]
    float* out = (float*)d_out;                 // pooled [B,D] ++ prob [B,S]

    cudaFuncSetAttribute(gemm_kv_pool_kernel,
                         cudaFuncAttributeMaxDynamicSharedMemorySize, SMEM_TOTAL);

    prep_w_kernel<<<(D * A + 255) / 256, 256>>>(W);
    gemm_kv_pool_kernel<<<B, 256, SMEM_TOTAL>>>(x, mask, bias, u);
    reduce_kernel<<<1, 1024>>>();
    combine_kernel<<<B, 128>>>(mask, out);
}

// round 10
// speedup vs baseline: 1.2499x; 1.1384x over previous
#include <cuda_runtime.h>
#include <cuda_fp16.h>
#include <cstdint>

// ---------------- problem constants ----------------
static constexpr int B = 512, S = 128, D = 512, A = 128;
static constexpr float EPS = 1e-7f;

// ---------------- device scratch (no allocs allowed) ----------------
__device__ __align__(16) __half g_wt[A * D];   // W^T fp16  [a][k]
__device__ float g_kv[B * S];
__device__ float g_mv;
__device__ __align__(16) float g_P1[B * D];    // sum_s x*exp(kv)*mask
__device__ __align__(16) float g_P2[B * D];    // sum_s x*mask

// ---------------- smem layout (R6 gemm structure + w1/w2) ----------------
// X staged as raw fp32: [2 buf][128 rows][72 f32] = 36864 B/buf
// W staged as fp16:     [2 buf][128 rows][72 h]   = 18432 B/buf
static constexpr int XROWB = 72 * 4;     // 288 B
static constexpr int WROWB = 72 * 2;     // 144 B
static constexpr int XBUF_B = 128 * XROWB;   // 36864
static constexpr int WBUF_B = 128 * WROWB;   // 18432
static constexpr int OFF_XF   = 0;
static constexpr int OFF_WH   = OFF_XF + 2 * XBUF_B;   // 73728
static constexpr int OFF_BIAS = OFF_WH + 2 * WBUF_B;   // 110592
static constexpr int OFF_U    = OFF_BIAS + 512;
static constexpr int OFF_PART = OFF_U + 512;           // float[128][2]
static constexpr int OFF_W1   = OFF_PART + 1024;       // exp(kv)*mask [128]
static constexpr int OFF_MASK = OFF_W1 + 512;          // mask [128]
static constexpr int SMEM_TOTAL = OFF_MASK + 512;      // 113664 (2 CTAs/SM)

// ---------------- baseline-ISA helpers (sm_100 plain) ----------------
__device__ __forceinline__ uint32_t smem_u32(const void* p) {
    return (uint32_t)__cvta_generic_to_shared(p);
}

#define CP_ASYNC16(dst, src) \
    asm volatile("cp.async.cg.shared.global [%0], [%1], 16;" :: "r"(dst), "l"(src))
#define CP_COMMIT() asm volatile("cp.async.commit_group;")
#define CP_WAIT_ALL() asm volatile("cp.async.wait_group 0;")

#define LDSM_X4(r, addr) \
    asm volatile("ldmatrix.sync.aligned.m8n8.x4.shared.b16 {%0,%1,%2,%3}, [%4];" \
        : "=r"((r)[0]), "=r"((r)[1]), "=r"((r)[2]), "=r"((r)[3]) : "r"(addr))

#define MMA_F16(d, a, b0, b1) \
    asm volatile("mma.sync.aligned.m16n8k16.row.col.f32.f16.f16.f32 " \
        "{%0,%1,%2,%3}, {%4,%5,%6,%7}, {%8,%9}, {%0,%1,%2,%3};" \
        : "+f"((d)[0]), "+f"((d)[1]), "+f"((d)[2]), "+f"((d)[3]) \
        : "r"((a)[0]), "r"((a)[1]), "r"((a)[2]), "r"((a)[3]), "r"(b0), "r"(b1))

__device__ __forceinline__ uint32_t f2h2(float a, float b) {
    __half2 h = __floats2half2_rn(a, b);
    return *(uint32_t*)&h;
}

__device__ __forceinline__ float fast_tanh(float x) {
    float a = fabsf(x);
    float t = __expf(-2.0f * a);
    float r = (1.0f - t) / (1.0f + t);
    return copysignf(r, x);
}

// ---------------- kernel 0: transpose W to fp16 ----------------
__global__ void prep_w_kernel(const float* __restrict__ W) {
    int idx = blockIdx.x * blockDim.x + threadIdx.x;
    if (idx < D * A) {
        int k = idx / A, a = idx % A;
        g_wt[a * D + k] = __float2half_rn(W[idx]);
    }
}

// ---------------- kernel 1: fused GEMM + tanh + kv + pooling partials -------
// Gemm phase is byte-identical to the measured-43us R6 kernel. Pool tail
// re-reads X from global: the CTA just streamed X[b], so it's L2-resident.
__global__ __launch_bounds__(256, 2)
void gemm_kv_pool_kernel(const float* __restrict__ x,
                         const float* __restrict__ mask,
                         const float* __restrict__ bias,
                         const float* __restrict__ u) {
    extern __shared__ char smem[];
    const uint32_t sb = smem_u32(smem);
    const int tid = threadIdx.x;
    const int wid = tid >> 5;
    const int l   = tid & 31;
    const int b   = blockIdx.x;

    if (tid < A) {
        *(float*)(smem + OFF_BIAS + tid * 4) = bias[tid];
        *(float*)(smem + OFF_U + tid * 4) = u[tid];
        *(float*)(smem + OFF_MASK + tid * 4) = mask[b * S + tid];
    }

    const int wm = wid >> 1, wn = wid & 1;
    const int m0 = wm * 32, n0 = wn * 64;

    const float* xb = x + (size_t)b * S * D;

    // A-fragment lane geometry (fp32 smem, LDS.64 + cvt)
    const int ar = l >> 2;
    const int ac = (l & 3) << 1;
    // B-fragment ldmatrix pointer (within a W buffer)
    const uint32_t bOff = (uint32_t)((n0 + ((l >> 4) << 3) + (l & 7)) * WROWB
                                     + (((l >> 3) & 1) << 3) * 2);

    float acc[2][8][4];
    #pragma unroll
    for (int mt = 0; mt < 2; mt++)
        #pragma unroll
        for (int nt = 0; nt < 8; nt++)
            #pragma unroll
            for (int q = 0; q < 4; q++) acc[mt][nt][q] = 0.0f;

    // ---- issue chunk 0 ----
    {
        #pragma unroll
        for (int t = 0; t < 8; t++) {
            int slot = tid + t * 256;
            int row = slot >> 4, j = slot & 15;
            CP_ASYNC16(sb + OFF_XF + row * XROWB + j * 16,
                       (const char*)(xb + (size_t)row * D) + j * 16);
        }
        #pragma unroll
        for (int t = 0; t < 4; t++) {
            int slot = tid + t * 256;
            int row = slot >> 3, j = slot & 7;
            CP_ASYNC16(sb + OFF_WH + row * WROWB + j * 16,
                       (const char*)(g_wt + (size_t)row * D) + j * 16);
        }
        CP_COMMIT();
    }

    #pragma unroll 1
    for (int c = 0; c < 8; c++) {
        CP_WAIT_ALL();
        __syncthreads();

        if (c < 7) {
            const int c64 = (c + 1) * 64;
            const uint32_t xB = sb + OFF_XF + ((c + 1) & 1) * XBUF_B;
            const uint32_t wB = sb + OFF_WH + ((c + 1) & 1) * WBUF_B;
            #pragma unroll
            for (int t = 0; t < 8; t++) {
                int slot = tid + t * 256;
                int row = slot >> 4, j = slot & 15;
                CP_ASYNC16(xB + row * XROWB + j * 16,
                           (const char*)(xb + (size_t)row * D + c64) + j * 16);
            }
            #pragma unroll
            for (int t = 0; t < 4; t++) {
                int slot = tid + t * 256;
                int row = slot >> 3, j = slot & 7;
                CP_ASYNC16(wB + row * WROWB + j * 16,
                           (const char*)(g_wt + (size_t)row * D + c64) + j * 16);
            }
            CP_COMMIT();
        }

        const uint32_t xF = sb + OFF_XF + (c & 1) * XBUF_B;
        const uint32_t wH = sb + OFF_WH + (c & 1) * WBUF_B;

        #pragma unroll
        for (int ks = 0; ks < 4; ks++) {
            const int kc = ks * 16;
            uint32_t ah[2][4], bb[4][4];
            #pragma unroll
            for (int mt = 0; mt < 2; mt++) {
                const uint32_t boff = (uint32_t)((m0 + mt * 16 + ar) * XROWB
                                                 + (kc + ac) * 4) + (xF - sb);
                float2 v0 = *(const float2*)(smem + boff);
                float2 v1 = *(const float2*)(smem + boff + 8 * XROWB);
                float2 v2 = *(const float2*)(smem + boff + 32);
                float2 v3 = *(const float2*)(smem + boff + 8 * XROWB + 32);
                ah[mt][0] = f2h2(v0.x, v0.y);
                ah[mt][1] = f2h2(v1.x, v1.y);
                ah[mt][2] = f2h2(v2.x, v2.y);
                ah[mt][3] = f2h2(v3.x, v3.y);
            }
            #pragma unroll
            for (int nb = 0; nb < 4; nb++)
                LDSM_X4(bb[nb], wH + bOff + nb * (16 * WROWB) + kc * 2);
            #pragma unroll
            for (int mt = 0; mt < 2; mt++)
                #pragma unroll
                for (int nb = 0; nb < 4; nb++) {
                    MMA_F16(acc[mt][2 * nb],     ah[mt], bb[nb][0], bb[nb][1]);
                    MMA_F16(acc[mt][2 * nb + 1], ah[mt], bb[nb][2], bb[nb][3]);
                }
        }
        __syncthreads();
    }

    // ---- kv epilogue ----
    float rs[2][2] = {{0.0f, 0.0f}, {0.0f, 0.0f}};
    #pragma unroll
    for (int mt = 0; mt < 2; mt++) {
        #pragma unroll
        for (int nt = 0; nt < 8; nt++) {
            int n = n0 + nt * 8 + ((l & 3) << 1);
            float b0v = *(const float*)(smem + OFF_BIAS + n * 4);
            float b1v = *(const float*)(smem + OFF_BIAS + (n + 1) * 4);
            float u0v = *(const float*)(smem + OFF_U + n * 4);
            float u1v = *(const float*)(smem + OFF_U + (n + 1) * 4);
            rs[mt][0] += fast_tanh(acc[mt][nt][0] + b0v) * u0v
                       + fast_tanh(acc[mt][nt][1] + b1v) * u1v;
            rs[mt][1] += fast_tanh(acc[mt][nt][2] + b0v) * u0v
                       + fast_tanh(acc[mt][nt][3] + b1v) * u1v;
        }
    }
    #pragma unroll
    for (int mt = 0; mt < 2; mt++)
        #pragma unroll
        for (int h = 0; h < 2; h++) {
            float v = rs[mt][h];
            v += __shfl_xor_sync(0xFFFFFFFFu, v, 1);
            v += __shfl_xor_sync(0xFFFFFFFFu, v, 2);
            if ((l & 3) == 0) {
                int row = m0 + mt * 16 + h * 8 + (l >> 2);
                *(float*)(smem + OFF_PART + (row * 2 + wn) * 4) = v;
            }
        }
    __syncthreads();
    if (tid < S) {
        float kv = *(const float*)(smem + OFF_PART + (tid * 2) * 4)
                 + *(const float*)(smem + OFF_PART + (tid * 2 + 1) * 4);
        g_kv[b * S + tid] = kv;
        float mk = *(const float*)(smem + OFF_MASK + tid * 4);
        *(float*)(smem + OFF_W1 + tid * 4) = __expf(kv) * mk;   // |kv| <= ~10
    }
    __syncthreads();

    // ---- pooling partials: re-read X from global (L2-hot), fp32 ----
    // thread owns d-pair {2*tid, 2*tid+1}
    float2 p1 = make_float2(0.f, 0.f), p2 = make_float2(0.f, 0.f);
    float2 q1 = make_float2(0.f, 0.f), q2 = make_float2(0.f, 0.f);
    #pragma unroll 4
    for (int s = 0; s < S; s += 2) {
        float2 va = *(const float2*)(xb + (size_t)s * D + tid * 2);
        float2 vb = *(const float2*)(xb + (size_t)(s + 1) * D + tid * 2);
        float w1a = *(const float*)(smem + OFF_W1 + s * 4);
        float w2a = *(const float*)(smem + OFF_MASK + s * 4);
        float w1b = *(const float*)(smem + OFF_W1 + (s + 1) * 4);
        float w2b = *(const float*)(smem + OFF_MASK + (s + 1) * 4);
        p1.x += va.x * w1a; p1.y += va.y * w1a;
        p2.x += va.x * w2a; p2.y += va.y * w2a;
        q1.x += vb.x * w1b; q1.y += vb.y * w1b;
        q2.x += vb.x * w2b; q2.y += vb.y * w2b;
    }
    *(float2*)(g_P1 + (size_t)b * D + tid * 2) = make_float2(p1.x + q1.x, p1.y + q1.y);
    *(float2*)(g_P2 + (size_t)b * D + tid * 2) = make_float2(p2.x + q2.x, p2.y + q2.y);
}

// ---------------- kernel 2: global sum of kv (double accum) ----------------
__global__ void reduce_kernel() {
    __shared__ double ssum[32];
    double acc = 0.0;
    for (int i = threadIdx.x; i < B * S; i += 1024)
        acc += (double)g_kv[i];
    #pragma unroll
    for (int o = 16; o > 0; o >>= 1)
        acc += __shfl_xor_sync(0xFFFFFFFFu, acc, o);
    if ((threadIdx.x & 31) == 0) ssum[threadIdx.x >> 5] = acc;
    __syncthreads();
    if (threadIdx.x < 32) {
        double v = ssum[threadIdx.x];
        #pragma unroll
        for (int o = 16; o > 0; o >>= 1)
            v += __shfl_xor_sync(0xFFFFFFFFu, v, o);
        if (threadIdx.x == 0) g_mv = (float)v;
    }
}

// ---------------- kernel 3: combine -> prob + pooled ----------------
__global__ __launch_bounds__(256)
void combine_kernel(const float* __restrict__ mask, float* __restrict__ out) {
    __shared__ float se[S];
    __shared__ float ssum;
    const int tid = threadIdx.x;
    const int b = blockIdx.x;
    const double mv = (double)g_mv;

    if (tid < S) {
        float kv = g_kv[b * S + tid];
        float mk = mask[b * S + tid];
        float e = (float)exp((double)kv - mv);
        se[tid] = (e + EPS) * mk;
    }
    __syncthreads();
    if (tid < 32) {
        float v = se[tid] + se[tid + 32] + se[tid + 64] + se[tid + 96];
        #pragma unroll
        for (int o = 16; o > 0; o >>= 1)
            v += __shfl_xor_sync(0xFFFFFFFFu, v, o);
        if (tid == 0) ssum = v;
    }
    __syncthreads();
    const double den = (double)ssum + (double)EPS;
    if (tid < S)
        out[B * D + b * S + tid] = (float)((double)se[tid] / den);   // prob

    const double c = exp(-mv);
    #pragma unroll
    for (int i = tid; i < D; i += 256) {
        double num = c * (double)g_P1[(size_t)b * D + i]
                   + (double)EPS * (double)g_P2[(size_t)b * D + i];
        out[b * D + i] = (float)(num / den);                          // pooled
    }
}

// ---------------- launcher ----------------
extern "C" void kernel_launch(void* const* d_in, const int* in_sizes, int n_in,
                              void* d_out, int out_size) {
    const float* x    = (const float*)d_in[0];  // inputs  [B,S,D]
    const float* mask = (const float*)d_in[1];  // mask    [B,S,1]
    const float* W    = (const float*)d_in[2];  // kernel  [D,A]
    const float* bias = (const float*)d_in[3];  // bias    [A]
    const float* u    = (const float*)d_in[4];  // u_ctx   [A,1]
    float* out = (float*)d_out;                 // pooled [B,D] ++ prob [B,S]

    cudaFuncSetAttribute(gemm_kv_pool_kernel,
                         cudaFuncAttributeMaxDynamicSharedMemorySize, SMEM_TOTAL);

    prep_w_kernel<<<(D * A + 255) / 256, 256>>>(W);
    gemm_kv_pool_kernel<<<B, 256, SMEM_TOTAL>>>(x, mask, bias, u);
    reduce_kernel<<<1, 1024>>>();
    combine_kernel<<<B, 256>>>(mask, out);
}

// round 11
// speedup vs baseline: 1.3234x; 1.0588x over previous
#include <cuda_runtime.h>
#include <cuda_fp16.h>
#include <cstdint>

// ---------------- problem constants ----------------
static constexpr int B = 512, S = 128, D = 512, A = 128;
static constexpr float EPS = 1e-7f;

// ---------------- device scratch (no allocs allowed) ----------------
__device__ __align__(16) __half g_wt[A * D];    // W^T fp16 [a][k]
__device__ float g_kv[B * S];
__device__ float g_mv;
__device__ __align__(16) float g_P1h[B * 2 * D];  // per-half sum_s x*exp(kv)*mask
__device__ __align__(16) float g_P2h[B * 2 * D];  // per-half sum_s x*mask

// ---------------- gemm tiling: CTA = (batch, half) -> 64 rows ----------------
static constexpr int MS     = 64;               // rows per CTA
static constexpr int KC     = 64;               // k per W chunk
static constexpr int NCHUNK = D / KC;           // 8

// X resident fp16: [64 rows][520 h] (512 data + 8 pad) = 1040 B/row
static constexpr int XROWB  = 520 * 2;          // 1040
static constexpr int XTOT_B = MS * XROWB;       // 66560
// W stage: [128 rows][72 h] = 144 B/row -> 18432 B, double-buffered
static constexpr int WROWB  = 72 * 2;
static constexpr int WBUF_B = 128 * WROWB;      // 18432
static constexpr int OFF_X    = 0;
static constexpr int OFF_W    = XTOT_B;                      // 66560
static constexpr int OFF_BIAS = OFF_W + 2 * WBUF_B;          // 103424
static constexpr int OFF_U    = OFF_BIAS + 512;
static constexpr int OFF_PART = OFF_U + 512;                 // float[64][4]
static constexpr int OFF_W1   = OFF_PART + 1024;             // exp(kv)*mask [64]
static constexpr int OFF_MASK = OFF_W1 + 256;                // mask [64]
static constexpr int SMEM_TOTAL = OFF_MASK + 256;            // 105984 (2 CTAs/SM)

// ---------------- baseline-ISA helpers (sm_100 plain) ----------------
__device__ __forceinline__ uint32_t smem_u32(const void* p) {
    return (uint32_t)__cvta_generic_to_shared(p);
}

#define CP_ASYNC16(dst, src) \
    asm volatile("cp.async.cg.shared.global [%0], [%1], 16;" :: "r"(dst), "l"(src))
#define CP_COMMIT() asm volatile("cp.async.commit_group;")
#define CP_WAIT_ALL() asm volatile("cp.async.wait_group 0;")

#define LDSM_X4(r, addr) \
    asm volatile("ldmatrix.sync.aligned.m8n8.x4.shared.b16 {%0,%1,%2,%3}, [%4];" \
        : "=r"((r)[0]), "=r"((r)[1]), "=r"((r)[2]), "=r"((r)[3]) : "r"(addr))

#define MMA_F16(d, a, b0, b1) \
    asm volatile("mma.sync.aligned.m16n8k16.row.col.f32.f16.f16.f32 " \
        "{%0,%1,%2,%3}, {%4,%5,%6,%7}, {%8,%9}, {%0,%1,%2,%3};" \
        : "+f"((d)[0]), "+f"((d)[1]), "+f"((d)[2]), "+f"((d)[3]) \
        : "r"((a)[0]), "r"((a)[1]), "r"((a)[2]), "r"((a)[3]), "r"(b0), "r"(b1))

__device__ __forceinline__ float fast_tanh(float x) {
    float a = fabsf(x);
    float t = __expf(-2.0f * a);
    float r = (1.0f - t) / (1.0f + t);
    return copysignf(r, x);
}

// ---------------- kernel 0: transpose W to fp16 ----------------
__global__ void prep_w_kernel(const float* __restrict__ W) {
    int idx = blockIdx.x * blockDim.x + threadIdx.x;
    if (idx < D * A) {
        int k = idx / A, a = idx % A;
        g_wt[a * D + k] = __float2half_rn(W[idx]);
    }
}

// ---------------- kernel 1: fused GEMM + tanh + kv + pooling ----------------
// CTA = (batch, half): 64 s-rows. X converted to fp16 and RESIDENT in smem.
// DRAM reads X exactly once; pool tail runs from smem. 2 CTAs/SM.
__global__ __launch_bounds__(256, 2)
void gemm_kv_pool_kernel(const float* __restrict__ x,
                         const float* __restrict__ mask,
                         const float* __restrict__ bias,
                         const float* __restrict__ u) {
    extern __shared__ char smem[];
    const uint32_t sb = smem_u32(smem);
    const int tid = threadIdx.x;
    const int wid = tid >> 5;
    const int l   = tid & 31;
    const int b    = blockIdx.x >> 1;
    const int half = blockIdx.x & 1;
    const int srow0 = half * MS;

    if (tid < A) {
        *(float*)(smem + OFF_BIAS + tid * 4) = bias[tid];
        *(float*)(smem + OFF_U + tid * 4) = u[tid];
    }
    if (tid < MS)
        *(float*)(smem + OFF_MASK + tid * 4) = mask[b * S + srow0 + tid];

    const int wm = wid >> 2, wn = wid & 3;       // 2 x 4 warp grid
    const int m0 = wm * 32, n0 = wn * 32;

    const float* xb = x + (size_t)(b * S + srow0) * D;

    // A ldmatrix pointer (within resident X)
    const uint32_t aOff = (uint32_t)((m0 + (l & 15)) * XROWB + ((l >> 4) << 3) * 2);
    // B ldmatrix pointer (within a W stage)
    const uint32_t bOff = (uint32_t)((n0 + ((l >> 4) << 3) + (l & 7)) * WROWB
                                     + (((l >> 3) & 1) << 3) * 2);

    // X LDG geometry: 1024 float4/chunk -> 4/thread (rows xr0 + t*16)
    const int xr0 = tid >> 4, xc4 = tid & 15;
    // W cp.async: 1024 ops/chunk -> 4/thread (rows wr0 + t*32)
    const int wr0 = tid >> 3, wj = tid & 7;

    float acc[2][4][4];
    #pragma unroll
    for (int mt = 0; mt < 2; mt++)
        #pragma unroll
        for (int nt = 0; nt < 4; nt++)
            #pragma unroll
            for (int q = 0; q < 4; q++) acc[mt][nt][q] = 0.0f;

    float4 xreg[4];
    auto loadX = [&](int c) {
        #pragma unroll
        for (int t = 0; t < 4; t++) {
            int row = xr0 + t * 16;
            xreg[t] = *(const float4*)(xb + (size_t)row * D + c * KC + xc4 * 4);
        }
    };
    auto storeX = [&](int c) {
        #pragma unroll
        for (int t = 0; t < 4; t++) {
            int row = xr0 + t * 16;
            __half2 h0 = __floats2half2_rn(xreg[t].x, xreg[t].y);
            __half2 h1 = __floats2half2_rn(xreg[t].z, xreg[t].w);
            *(uint2*)(smem + OFF_X + row * XROWB + (c * KC + xc4 * 4) * 2) =
                make_uint2(*(uint32_t*)&h0, *(uint32_t*)&h1);
        }
    };

    // ---- prologue: X chunk 0 LDGs; W chunk 0 cp.async ----
    loadX(0);
    {
        const uint32_t wB = sb + OFF_W;
        #pragma unroll
        for (int t = 0; t < 4; t++) {
            int row = wr0 + t * 32;
            CP_ASYNC16(wB + row * WROWB + wj * 16,
                       (const char*)(g_wt + (size_t)row * D) + wj * 16);
        }
        CP_COMMIT();
    }

    #pragma unroll 1
    for (int c = 0; c < NCHUNK; c++) {
        storeX(c);                          // cvt+STS chunk c (resident)
        if (c + 1 < NCHUNK) loadX(c + 1);   // LDGs drain during MMA
        CP_WAIT_ALL();                      // W chunk c resident
        __syncthreads();                    // X_c + W_c visible

        if (c + 1 < NCHUNK) {
            const uint32_t wB = sb + OFF_W + ((c + 1) & 1) * WBUF_B;
            #pragma unroll
            for (int t = 0; t < 4; t++) {
                int row = wr0 + t * 32;
                CP_ASYNC16(wB + row * WROWB + wj * 16,
                           (const char*)(g_wt + (size_t)row * D + (c + 1) * KC) + wj * 16);
            }
            CP_COMMIT();
        }

        const uint32_t wH = sb + OFF_W + (c & 1) * WBUF_B;
        #pragma unroll
        for (int ks = 0; ks < 4; ks++) {
            const int g = c * 4 + ks;
            uint32_t ah[2][4], bb[2][4];
            LDSM_X4(ah[0], sb + OFF_X + aOff + g * 32);
            LDSM_X4(ah[1], sb + OFF_X + aOff + 16 * XROWB + g * 32);
            LDSM_X4(bb[0], wH + bOff + ks * 32);
            LDSM_X4(bb[1], wH + bOff + 16 * WROWB + ks * 32);
            #pragma unroll
            for (int mt = 0; mt < 2; mt++)
                #pragma unroll
                for (int nb = 0; nb < 2; nb++) {
                    MMA_F16(acc[mt][2 * nb],     ah[mt], bb[nb][0], bb[nb][1]);
                    MMA_F16(acc[mt][2 * nb + 1], ah[mt], bb[nb][2], bb[nb][3]);
                }
        }
        __syncthreads();                    // MMA done before next STS/W-overwrite
    }

    // ---- kv epilogue: kv[m] = sum_n tanh(C[m][n] + bias[n]) * u[n] ----
    float rs[2][2] = {{0.0f, 0.0f}, {0.0f, 0.0f}};
    #pragma unroll
    for (int mt = 0; mt < 2; mt++) {
        #pragma unroll
        for (int nt = 0; nt < 4; nt++) {
            int n = n0 + nt * 8 + ((l & 3) << 1);
            float b0v = *(const float*)(smem + OFF_BIAS + n * 4);
            float b1v = *(const float*)(smem + OFF_BIAS + (n + 1) * 4);
            float u0v = *(const float*)(smem + OFF_U + n * 4);
            float u1v = *(const float*)(smem + OFF_U + (n + 1) * 4);
            rs[mt][0] += fast_tanh(acc[mt][nt][0] + b0v) * u0v
                       + fast_tanh(acc[mt][nt][1] + b1v) * u1v;
            rs[mt][1] += fast_tanh(acc[mt][nt][2] + b0v) * u0v
                       + fast_tanh(acc[mt][nt][3] + b1v) * u1v;
        }
    }
    #pragma unroll
    for (int mt = 0; mt < 2; mt++)
        #pragma unroll
        for (int h = 0; h < 2; h++) {
            float v = rs[mt][h];
            v += __shfl_xor_sync(0xFFFFFFFFu, v, 1);
            v += __shfl_xor_sync(0xFFFFFFFFu, v, 2);
            if ((l & 3) == 0) {
                int row = m0 + mt * 16 + h * 8 + (l >> 2);   // 0..63
                *(float*)(smem + OFF_PART + (row * 4 + wn) * 4) = v;
            }
        }
    __syncthreads();
    if (tid < MS) {
        float kv = *(const float*)(smem + OFF_PART + (tid * 4) * 4)
                 + *(const float*)(smem + OFF_PART + (tid * 4 + 1) * 4)
                 + *(const float*)(smem + OFF_PART + (tid * 4 + 2) * 4)
                 + *(const float*)(smem + OFF_PART + (tid * 4 + 3) * 4);
        g_kv[b * S + srow0 + tid] = kv;
        float mk = *(const float*)(smem + OFF_MASK + tid * 4);
        *(float*)(smem + OFF_W1 + tid * 4) = __expf(kv) * mk;   // |kv| <= ~10
    }
    __syncthreads();

    // ---- pooling partials from resident fp16 X (smem only) ----
    // thread owns d-pair {2*tid, 2*tid+1}
    float2 p1 = make_float2(0.f, 0.f), p2 = make_float2(0.f, 0.f);
    #pragma unroll 8
    for (int s = 0; s < MS; s++) {
        uint32_t packed = *(const uint32_t*)(smem + OFF_X + s * XROWB + tid * 4);
        float2 f = __half22float2(*(const __half2*)&packed);
        float w1 = *(const float*)(smem + OFF_W1 + s * 4);
        float w2 = *(const float*)(smem + OFF_MASK + s * 4);
        p1.x += f.x * w1; p1.y += f.y * w1;
        p2.x += f.x * w2; p2.y += f.y * w2;
    }
    const size_t po = (size_t)(b * 2 + half) * D + tid * 2;
    *(float2*)(g_P1h + po) = p1;
    *(float2*)(g_P2h + po) = p2;
}

// ---------------- kernel 2: global sum of kv (double accum) ----------------
__global__ void reduce_kernel() {
    __shared__ double ssum[32];
    double acc = 0.0;
    for (int i = threadIdx.x; i < B * S; i += 1024)
        acc += (double)g_kv[i];
    #pragma unroll
    for (int o = 16; o > 0; o >>= 1)
        acc += __shfl_xor_sync(0xFFFFFFFFu, acc, o);
    if ((threadIdx.x & 31) == 0) ssum[threadIdx.x >> 5] = acc;
    __syncthreads();
    if (threadIdx.x < 32) {
        double v = ssum[threadIdx.x];
        #pragma unroll
        for (int o = 16; o > 0; o >>= 1)
            v += __shfl_xor_sync(0xFFFFFFFFu, v, o);
        if (threadIdx.x == 0) g_mv = (float)v;
    }
}

// ---------------- kernel 3: combine -> prob + pooled ----------------
__global__ __launch_bounds__(256)
void combine_kernel(const float* __restrict__ mask, float* __restrict__ out) {
    __shared__ float se[S];
    __shared__ float ssum;
    const int tid = threadIdx.x;
    const int b = blockIdx.x;
    const double mv = (double)g_mv;

    if (tid < S) {
        float kv = g_kv[b * S + tid];
        float mk = mask[b * S + tid];
        float e = (float)exp((double)kv - mv);
        se[tid] = (e + EPS) * mk;
    }
    __syncthreads();
    if (tid < 32) {
        float v = se[tid] + se[tid + 32] + se[tid + 64] + se[tid + 96];
        #pragma unroll
        for (int o = 16; o > 0; o >>= 1)
            v += __shfl_xor_sync(0xFFFFFFFFu, v, o);
        if (tid == 0) ssum = v;
    }
    __syncthreads();
    const double den = (double)ssum + (double)EPS;
    if (tid < S)
        out[B * D + b * S + tid] = (float)((double)se[tid] / den);   // prob

    const double c = exp(-mv);
    #pragma unroll
    for (int i = tid; i < D; i += 256) {
        double p1 = (double)g_P1h[(size_t)(b * 2) * D + i]
                  + (double)g_P1h[(size_t)(b * 2 + 1) * D + i];
        double p2 = (double)g_P2h[(size_t)(b * 2) * D + i]
                  + (double)g_P2h[(size_t)(b * 2 + 1) * D + i];
        out[b * D + i] = (float)((c * p1 + (double)EPS * p2) / den); // pooled
    }
}

// ---------------- launcher ----------------
extern "C" void kernel_launch(void* const* d_in, const int* in_sizes, int n_in,
                              void* d_out, int out_size) {
    const float* x    = (const float*)d_in[0];  // inputs  [B,S,D]
    const float* mask = (const float*)d_in[1];  // mask    [B,S,1]
    const float* W    = (const float*)d_in[2];  // kernel  [D,A]
    const float* bias = (const float*)d_in[3];  // bias    [A]
    const float* u    = (const float*)d_in[4];  // u_ctx   [A,1]
    float* out = (float*)d_out;                 // pooled [B,D] ++ prob [B,S]

    cudaFuncSetAttribute(gemm_kv_pool_kernel,
                         cudaFuncAttributeMaxDynamicSharedMemorySize, SMEM_TOTAL);

    prep_w_kernel<<<(D * A + 255) / 256, 256>>>(W);
    gemm_kv_pool_kernel<<<B * 2, 256, SMEM_TOTAL>>>(x, mask, bias, u);
    reduce_kernel<<<1, 1024>>>();
    combine_kernel<<<B, 256>>>(mask, out);
}